// round 13
// baseline (speedup 1.0000x reference)
#include <cuda_runtime.h>
#include <math.h>

#define B_     256
#define T_     1024
#define DIN    32
#define DH     200
#define DOUT   2
#define CHUNK  32
#define NCHUNK (T_ / CHUNK)
#define NTHR   160          // 4 producer warps + 1 consumer warp
#define NPROD  128
#define NACT   100          // threads 0..99 each own units 2t, 2t+1
#define PADR   101          // float2 row stride for partials (conflict degree 2)

#define PART_F2   (CHUNK * PADR)                      // 3232 float2 per buffer
#define OFF_PART  0
#define OFF_MBAR  (2 * PART_F2 * 8)                   // 51712
#define SMEM_TOTAL (OFF_MBAR + 64)

__device__ __forceinline__ unsigned sm_u32(const void* p) {
    return (unsigned)__cvta_generic_to_shared(p);
}
__device__ __forceinline__ unsigned long long pack2(float x, float y) {
    unsigned long long v;
    asm("mov.b64 %0, {%1, %2};" : "=l"(v) : "f"(x), "f"(y));
    return v;
}
__device__ __forceinline__ void fma2(unsigned long long& d,
                                     unsigned long long a, unsigned long long b) {
    asm("fma.rn.f32x2 %0, %1, %2, %0;" : "+l"(d) : "l"(a), "l"(b));
}
__device__ __forceinline__ float sum2(unsigned long long a, unsigned long long b) {
    unsigned long long s;
    asm("add.rn.f32x2 %0, %1, %2;" : "=l"(s) : "l"(a), "l"(b));
    float lo, hi;
    asm("mov.b64 {%0, %1}, %2;" : "=f"(lo), "=f"(hi) : "l"(s));
    return lo + hi;
}
// Full 128-byte step load straight from global (read-only path), 8x LDG.128.
__device__ __forceinline__ void ld16g(unsigned long long* xr, const float* g) {
    asm volatile(
        "ld.global.nc.v2.u64 {%0, %1}, [%16];\n\t"
        "ld.global.nc.v2.u64 {%2, %3}, [%16+16];\n\t"
        "ld.global.nc.v2.u64 {%4, %5}, [%16+32];\n\t"
        "ld.global.nc.v2.u64 {%6, %7}, [%16+48];\n\t"
        "ld.global.nc.v2.u64 {%8, %9}, [%16+64];\n\t"
        "ld.global.nc.v2.u64 {%10, %11}, [%16+80];\n\t"
        "ld.global.nc.v2.u64 {%12, %13}, [%16+96];\n\t"
        "ld.global.nc.v2.u64 {%14, %15}, [%16+112];"
        : "=l"(xr[0]),  "=l"(xr[1]),  "=l"(xr[2]),  "=l"(xr[3]),
          "=l"(xr[4]),  "=l"(xr[5]),  "=l"(xr[6]),  "=l"(xr[7]),
          "=l"(xr[8]),  "=l"(xr[9]),  "=l"(xr[10]), "=l"(xr[11]),
          "=l"(xr[12]), "=l"(xr[13]), "=l"(xr[14]), "=l"(xr[15])
        : "l"(g));
}
__device__ __forceinline__ void prefetchL2(const float* g) {
    asm volatile("prefetch.global.L2 [%0];" :: "l"(g));
}
__device__ __forceinline__ void mbar_init(unsigned a, unsigned cnt) {
    asm volatile("mbarrier.init.shared.b64 [%0], %1;" :: "r"(a), "r"(cnt));
}
__device__ __forceinline__ void mbar_arrive(unsigned a) {
    asm volatile("mbarrier.arrive.release.cta.shared::cta.b64 _, [%0];" :: "r"(a) : "memory");
}
__device__ __forceinline__ void mbar_wait(unsigned a, unsigned parity) {
    asm volatile(
        "{\n\t.reg .pred P;\n\t"
        "WL_%=:\n\t"
        "mbarrier.try_wait.parity.acquire.cta.shared::cta.b64 P, [%0], %1, 0x989680;\n\t"
        "@P bra.uni WD_%=;\n\t"
        "bra.uni WL_%=;\n\t"
        "WD_%=:\n\t}"
        :: "r"(a), "r"(parity) : "memory");
}

__global__ __launch_bounds__(NTHR, 2)
void snn_kernel(const float* __restrict__ x,  const float* __restrict__ W1,
                const float* __restrict__ b1, const float* __restrict__ W2,
                const float* __restrict__ b2, float* __restrict__ out,
                float a1, float a2)
{
    extern __shared__ __align__(16) unsigned char smem_raw[];
    float2* part = (float2*)(smem_raw + OFF_PART);
    const unsigned smem_base = sm_u32(smem_raw);
    const unsigned mbF0 = smem_base + OFF_MBAR;
    const unsigned mbF1 = mbF0 + 8;
    const unsigned mbE0 = mbF0 + 16;
    const unsigned mbE1 = mbF0 + 24;

    const int b   = blockIdx.x;
    const int tid = threadIdx.x;

    // output layout: output[B,2] | s1s[B,T,DH] | m1s[B,T,DH] | s2s[B,T,2] | m2s[B,T,2]
    float* out_o  = out;
    float* out_s1 = out + (size_t)B_ * DOUT;
    float* out_m1 = out_s1 + (size_t)B_ * T_ * DH;
    float* out_s2 = out_m1 + (size_t)B_ * T_ * DH;
    float* out_m2 = out_s2 + (size_t)B_ * T_ * DOUT;

    const float* xrow = x + (size_t)b * T_ * DIN;
    float* s1p = out_s1 + (size_t)b * T_ * DH;
    float* m1p = out_m1 + (size_t)b * T_ * DH;
    float* s2p = out_s2 + (size_t)b * T_ * DOUT;
    float* m2p = out_m2 + (size_t)b * T_ * DOUT;

    if (tid == 0) {
        mbar_init(mbF0, 4); mbar_init(mbF1, 4);   // one arrive per producer warp
        mbar_init(mbE0, 1); mbar_init(mbE1, 1);   // one elected consumer arrive
    }

    // ---- producer weights: 2 units per thread, W1 columns packed over k-pairs ----
    unsigned long long wpA[DIN / 2], wpB[DIN / 2];
    float w20A = 0.f, w21A = 0.f, w20B = 0.f, w21B = 0.f;
    unsigned long long accInitA = 0, accInitB = 0;
    const unsigned long long zero64 = pack2(0.f, 0.f);
    const bool lact = (tid < NACT);
    const int j0 = 2 * tid;
    if (lact) {
        #pragma unroll
        for (int kk = 0; kk < DIN / 2; kk++) {
            wpA[kk] = pack2(W1[(2 * kk) * DH + j0],     W1[(2 * kk + 1) * DH + j0]);
            wpB[kk] = pack2(W1[(2 * kk) * DH + j0 + 1], W1[(2 * kk + 1) * DH + j0 + 1]);
        }
        w20A = W2[j0 * 2 + 0];       w21A = W2[j0 * 2 + 1];
        w20B = W2[(j0 + 1) * 2 + 0]; w21B = W2[(j0 + 1) * 2 + 1];
        accInitA = pack2(b1[j0], 0.f);
        accInitB = pack2(b1[j0 + 1], 0.f);
    }
    __syncthreads();   // publish mbarrier init

    if (tid < NPROD) {
        // ================= PRODUCERS (layer 1) =================
        float m1A = 0.f, m1B = 0.f;

        for (int ch = 0; ch < NCHUNK; ch++) {
            const int buf = ch & 1;
            const int u   = ch >> 1;
            if (ch >= 2)
                mbar_wait(buf ? mbE1 : mbE0, (unsigned)((u & 1) ^ 1));

            if (lact) {
                const float* xg = xrow + (size_t)ch * CHUNK * DIN;
                float*  pS = s1p + (size_t)ch * CHUNK * DH + j0;
                float*  pM = m1p + (size_t)ch * CHUNK * DH + j0;
                float2* pP = part + (size_t)buf * PART_F2 + tid;

                // one-full-step-ahead register pipeline straight from global
                unsigned long long x0[16], x1[16];
                ld16g(x0, xg);                        // step 0
                const int gbase = ch * CHUNK;

                for (int tt = 0; tt < CHUNK; tt += 2) {
                    // rolling L2 prefetch ~4 steps ahead (covers leading-warp miss)
                    if (gbase + tt + 4 < T_)
                        prefetchL2(xg + (tt + 4) * DIN);

                    // ---- step tt (x0); prefetch tt+1 into x1 first ----
                    ld16g(x1, xg + (tt + 1) * DIN);
                    {
                        unsigned long long a0 = accInitA, a1r = zero64;
                        unsigned long long bb0 = accInitB, bb1 = zero64;
                        #pragma unroll
                        for (int q = 0; q < DIN / 4; q++) {
                            fma2(a0,  x0[2 * q],     wpA[2 * q]);
                            fma2(a1r, x0[2 * q + 1], wpA[2 * q + 1]);
                            fma2(bb0, x0[2 * q],     wpB[2 * q]);
                            fma2(bb1, x0[2 * q + 1], wpB[2 * q + 1]);
                        }
                        const float driveA = sum2(a0, a1r);
                        const float driveB = sum2(bb0, bb1);
                        m1A = fmaf(m1A, a1, driveA);
                        const float s1A = (m1A > 0.5f) ? 1.0f : 0.0f;
                        m1A = fmaf(s1A, -0.5f, m1A);
                        m1B = fmaf(m1B, a1, driveB);
                        const float s1B = (m1B > 0.5f) ? 1.0f : 0.0f;
                        m1B = fmaf(s1B, -0.5f, m1B);

                        __stcs((float2*)pS, make_float2(s1A, s1B));  pS += DH;
                        __stcs((float2*)pM, make_float2(m1A, m1B));  pM += DH;
                        float px = s1A * w20A; px = fmaf(s1B, w20B, px);
                        float py = s1A * w21A; py = fmaf(s1B, w21B, py);
                        *pP = make_float2(px, py);
                        pP += PADR;
                    }
                    // ---- step tt+1 (x1); prefetch tt+2 into x0 first ----
                    if (tt + 2 < CHUNK)
                        ld16g(x0, xg + (tt + 2) * DIN);
                    {
                        unsigned long long a0 = accInitA, a1r = zero64;
                        unsigned long long bb0 = accInitB, bb1 = zero64;
                        #pragma unroll
                        for (int q = 0; q < DIN / 4; q++) {
                            fma2(a0,  x1[2 * q],     wpA[2 * q]);
                            fma2(a1r, x1[2 * q + 1], wpA[2 * q + 1]);
                            fma2(bb0, x1[2 * q],     wpB[2 * q]);
                            fma2(bb1, x1[2 * q + 1], wpB[2 * q + 1]);
                        }
                        const float driveA = sum2(a0, a1r);
                        const float driveB = sum2(bb0, bb1);
                        m1A = fmaf(m1A, a1, driveA);
                        const float s1A = (m1A > 0.5f) ? 1.0f : 0.0f;
                        m1A = fmaf(s1A, -0.5f, m1A);
                        m1B = fmaf(m1B, a1, driveB);
                        const float s1B = (m1B > 0.5f) ? 1.0f : 0.0f;
                        m1B = fmaf(s1B, -0.5f, m1B);

                        __stcs((float2*)pS, make_float2(s1A, s1B));  pS += DH;
                        __stcs((float2*)pM, make_float2(m1A, m1B));  pM += DH;
                        float px = s1A * w20A; px = fmaf(s1B, w20B, px);
                        float py = s1A * w21A; py = fmaf(s1B, w21B, py);
                        *pP = make_float2(px, py);
                        pP += PADR;
                    }
                }
            }
            __syncwarp();
            if ((tid & 31) == 0)
                mbar_arrive(buf ? mbF1 : mbF0);   // release covers warp's stores
        }
    } else {
        // ================= CONSUMER (layer 2) =================
        const int lane = tid - NPROD;             // lane = timestep within chunk
        const float b2x = b2[0], b2y = b2[1];
        float m2x = 0.f, m2y = 0.f, os0 = 0.f, os1 = 0.f;
        float f0 = 0.f, f1 = 0.f;                 // m2s[t=0] per channel

        for (int ch = 0; ch < NCHUNK; ch++) {
            const int buf = ch & 1;
            const int u   = ch >> 1;
            mbar_wait(buf ? mbF1 : mbF0, (unsigned)(u & 1));

            // lane tt sums 100 pre-reduced float2 partials for its step
            const float2* pf = part + (size_t)buf * PART_F2 + lane * PADR;
            float ax0 = 0.f, ay0 = 0.f, ax1 = 0.f, ay1 = 0.f;
            #pragma unroll 4
            for (int j = 0; j < NACT; j += 2) {
                float2 v0 = pf[j], v1 = pf[j + 1];
                ax0 += v0.x; ay0 += v0.y;
                ax1 += v1.x; ay1 += v1.y;
            }
            const float sx = ax0 + ax1;           // drive for output 0, step=lane
            const float sy = ay0 + ay1;           // drive for output 1, step=lane

            __syncwarp();
            if (lane == 0)
                mbar_arrive(buf ? mbE1 : mbE0);   // part[buf] free once gathered

            // hoist all shuffles out of the serial chain
            float rA[CHUNK], rB[CHUNK];
            #pragma unroll
            for (int t2 = 0; t2 < CHUNK; t2++) {
                rA[t2] = __shfl_sync(0xffffffffu, sx, t2) + b2x;
                rB[t2] = __shfl_sync(0xffffffffu, sy, t2) + b2y;
            }

            // tight serial recurrence, both channels in-lane; lane t2 captures step t2
            float capS0 = 0.f, capS1 = 0.f, capM0 = 0.f, capM1 = 0.f;
            #pragma unroll
            for (int t2 = 0; t2 < CHUNK; t2++) {
                m2x = fmaf(m2x, a2, rA[t2]);
                const float sA = (m2x > 1.0f) ? 1.0f : 0.0f;
                m2x -= sA;
                m2y = fmaf(m2y, a2, rB[t2]);
                const float sB = (m2y > 1.0f) ? 1.0f : 0.0f;
                m2y -= sB;
                os0 += m2x; os1 += m2y;
                if (lane == t2) { capS0 = sA; capS1 = sB; capM0 = m2x; capM1 = m2y; }
            }
            // coalesced per-step stores: lane t2 <-> global step ch*CHUNK + t2
            const int gt = ch * CHUNK + lane;
            __stcs((float2*)(s2p + (size_t)gt * DOUT), make_float2(capS0, capS1));
            __stcs((float2*)(m2p + (size_t)gt * DOUT), make_float2(capM0, capM1));

            if (ch == 0) {                         // remember m2s[t=0] (lane 0's capture)
                f0 = __shfl_sync(0xffffffffu, capM0, 0);
                f1 = __shfl_sync(0xffffffffu, capM1, 0);
            }
        }
        if (lane == 0) {
            out_o[b * DOUT + 0] = (os0 - f0) * (1.0f / (float)T_);
            out_o[b * DOUT + 1] = (os1 - f1) * (1.0f / (float)T_);
        }
    }
}

extern "C" void kernel_launch(void* const* d_in, const int* in_sizes, int n_in,
                              void* d_out, int out_size) {
    const float* x  = (const float*)d_in[0];
    const float* W1 = (const float*)d_in[1];
    const float* b1 = (const float*)d_in[2];
    const float* W2 = (const float*)d_in[3];
    const float* b2 = (const float*)d_in[4];

    const float a1 = (float)exp((double)(-1.0f / 10.0f));
    const float a2 = (float)exp((double)(-1.0f / 20.0f));

    cudaFuncSetAttribute(snn_kernel,
                         cudaFuncAttributeMaxDynamicSharedMemorySize, SMEM_TOTAL);
    snn_kernel<<<B_, NTHR, SMEM_TOTAL>>>(x, W1, b1, W2, b2, (float*)d_out, a1, a2);
}

// round 15
// speedup vs baseline: 1.2456x; 1.2456x over previous
#include <cuda_runtime.h>
#include <math.h>

#define B_     256
#define T_     1024
#define DIN    32
#define DH     200
#define DOUT   2
#define CHUNK  32
#define HALF   16
#define NCHUNK (T_ / CHUNK)
#define NTHR   160          // 4 producer warps + 1 consumer warp
#define NPROD  128
#define NACT   100          // threads 0..99 each own units 2t, 2t+1
#define PADR   101          // float2 row stride for partials (conflict degree 2)

#define XS_BYTES   (CHUNK * DIN * 4)                  // 4096 per slot, 2 slots
#define TILE_B     (HALF * DH * 4)                    // 12800 bytes per sub-tile
#define PART_F2    (CHUNK * PADR)                     // 3232 float2 per buffer
#define OFF_XS     0                                  // 2 x 4096 = 8192
#define OFF_S1T    8192                               // 2 x 12800 = 25600
#define OFF_M1T    33792                              // 2 x 12800 = 25600
#define OFF_PART   59392                              // 2 x 25856 = 51712
#define OFF_MBAR   111104
#define SMEM_TOTAL 111168

__device__ __forceinline__ unsigned sm_u32(const void* p) {
    return (unsigned)__cvta_generic_to_shared(p);
}
__device__ __forceinline__ void cp16(unsigned saddr, const void* g) {
    asm volatile("cp.async.ca.shared.global [%0], [%1], 16;" :: "r"(saddr), "l"(g));
}
__device__ __forceinline__ void bulk_store(const void* gdst, unsigned ssrc, unsigned bytes) {
    asm volatile("cp.async.bulk.global.shared::cta.bulk_group [%0], [%1], %2;"
                 :: "l"(gdst), "r"(ssrc), "r"(bytes) : "memory");
}
__device__ __forceinline__ unsigned long long pack2(float x, float y) {
    unsigned long long v;
    asm("mov.b64 %0, {%1, %2};" : "=l"(v) : "f"(x), "f"(y));
    return v;
}
__device__ __forceinline__ void fma2(unsigned long long& d,
                                     unsigned long long a, unsigned long long b) {
    asm("fma.rn.f32x2 %0, %1, %2, %0;" : "+l"(d) : "l"(a), "l"(b));
}
__device__ __forceinline__ float sum2(unsigned long long a, unsigned long long b) {
    unsigned long long s;
    asm("add.rn.f32x2 %0, %1, %2;" : "=l"(s) : "l"(a), "l"(b));
    float lo, hi;
    asm("mov.b64 {%0, %1}, %2;" : "=f"(lo), "=f"(hi) : "l"(s));
    return lo + hi;
}
// Full 128-byte step load (16 u64). volatile + clobber: never crosses barriers.
__device__ __forceinline__ void ld16v(unsigned long long* xr, unsigned addr) {
    asm volatile(
        "ld.shared.v2.b64 {%0, %1}, [%16];\n\t"
        "ld.shared.v2.b64 {%2, %3}, [%17];\n\t"
        "ld.shared.v2.b64 {%4, %5}, [%18];\n\t"
        "ld.shared.v2.b64 {%6, %7}, [%19];\n\t"
        "ld.shared.v2.b64 {%8, %9}, [%20];\n\t"
        "ld.shared.v2.b64 {%10, %11}, [%21];\n\t"
        "ld.shared.v2.b64 {%12, %13}, [%22];\n\t"
        "ld.shared.v2.b64 {%14, %15}, [%23];"
        : "=l"(xr[0]),  "=l"(xr[1]),  "=l"(xr[2]),  "=l"(xr[3]),
          "=l"(xr[4]),  "=l"(xr[5]),  "=l"(xr[6]),  "=l"(xr[7]),
          "=l"(xr[8]),  "=l"(xr[9]),  "=l"(xr[10]), "=l"(xr[11]),
          "=l"(xr[12]), "=l"(xr[13]), "=l"(xr[14]), "=l"(xr[15])
        : "r"(addr),      "r"(addr + 16), "r"(addr + 32), "r"(addr + 48),
          "r"(addr + 64), "r"(addr + 80), "r"(addr + 96), "r"(addr + 112)
        : "memory");
}
__device__ __forceinline__ void mbar_init(unsigned a, unsigned cnt) {
    asm volatile("mbarrier.init.shared.b64 [%0], %1;" :: "r"(a), "r"(cnt));
}
__device__ __forceinline__ void mbar_arrive(unsigned a) {
    asm volatile("mbarrier.arrive.release.cta.shared::cta.b64 _, [%0];" :: "r"(a) : "memory");
}
__device__ __forceinline__ void mbar_wait(unsigned a, unsigned parity) {
    asm volatile(
        "{\n\t.reg .pred P;\n\t"
        "WL_%=:\n\t"
        "mbarrier.try_wait.parity.acquire.cta.shared::cta.b64 P, [%0], %1, 0x989680;\n\t"
        "@P bra.uni WD_%=;\n\t"
        "bra.uni WL_%=;\n\t"
        "WD_%=:\n\t}"
        :: "r"(a), "r"(parity) : "memory");
}

__global__ __launch_bounds__(NTHR, 2)
void snn_kernel(const float* __restrict__ x,  const float* __restrict__ W1,
                const float* __restrict__ b1, const float* __restrict__ W2,
                const float* __restrict__ b2, float* __restrict__ out,
                float a1, float a2)
{
    extern __shared__ __align__(16) unsigned char smem_raw[];
    float2* part = (float2*)(smem_raw + OFF_PART);
    const unsigned smem_base = sm_u32(smem_raw);
    const unsigned xs_sa = smem_base + OFF_XS;
    const unsigned mbF0 = smem_base + OFF_MBAR;
    const unsigned mbF1 = mbF0 + 8;
    const unsigned mbE0 = mbF0 + 16;
    const unsigned mbE1 = mbF0 + 24;

    const int b   = blockIdx.x;
    const int tid = threadIdx.x;

    // output layout: output[B,2] | s1s[B,T,DH] | m1s[B,T,DH] | s2s[B,T,2] | m2s[B,T,2]
    float* out_o  = out;
    float* out_s1 = out + (size_t)B_ * DOUT;
    float* out_m1 = out_s1 + (size_t)B_ * T_ * DH;
    float* out_s2 = out_m1 + (size_t)B_ * T_ * DH;
    float* out_m2 = out_s2 + (size_t)B_ * T_ * DOUT;

    const float* xrow = x + (size_t)b * T_ * DIN;
    float* s1p = out_s1 + (size_t)b * T_ * DH;
    float* m1p = out_m1 + (size_t)b * T_ * DH;
    float* s2p = out_s2 + (size_t)b * T_ * DOUT;
    float* m2p = out_m2 + (size_t)b * T_ * DOUT;

    if (tid == 0) {
        mbar_init(mbF0, 4); mbar_init(mbF1, 4);   // partials full (per-warp elected)
        mbar_init(mbE0, 1); mbar_init(mbE1, 1);   // partials free (consumer elected)
    }

    // ---- producer weights: 2 units per thread, W1 columns packed over k-pairs ----
    unsigned long long wpA[DIN / 2], wpB[DIN / 2];
    float w20A = 0.f, w21A = 0.f, w20B = 0.f, w21B = 0.f;
    unsigned long long accInitA = 0, accInitB = 0;
    const unsigned long long zero64 = pack2(0.f, 0.f);
    const bool lact = (tid < NACT);
    const int j0 = 2 * tid;
    if (lact) {
        #pragma unroll
        for (int kk = 0; kk < DIN / 2; kk++) {
            wpA[kk] = pack2(W1[(2 * kk) * DH + j0],     W1[(2 * kk + 1) * DH + j0]);
            wpB[kk] = pack2(W1[(2 * kk) * DH + j0 + 1], W1[(2 * kk + 1) * DH + j0 + 1]);
        }
        w20A = W2[j0 * 2 + 0];       w21A = W2[j0 * 2 + 1];
        w20B = W2[(j0 + 1) * 2 + 0]; w21B = W2[(j0 + 1) * 2 + 1];
        accInitA = pack2(b1[j0], 0.f);
        accInitB = pack2(b1[j0 + 1], 0.f);
    }
    __syncthreads();   // publish mbarrier init

    if (tid < NPROD) {
        // ================= PRODUCERS (layer 1) =================
        // prefetch x chunk 0 into slot 0
        cp16(xs_sa + 0 * XS_BYTES + tid * 32,      xrow + tid * 8);
        cp16(xs_sa + 0 * XS_BYTES + tid * 32 + 16, xrow + tid * 8 + 4);
        asm volatile("cp.async.commit_group;");

        float m1A = 0.f, m1B = 0.f;

        // per-step body on x buffer XB at step index ST (within chunk),
        // writing into smem tile row pointers pS/pM and partial pointer pP
        #define STEP_BODY(XB) do {                                                   \
            unsigned long long a0 = accInitA, a1r = zero64;                          \
            unsigned long long bb0 = accInitB, bb1 = zero64;                         \
            _Pragma("unroll")                                                        \
            for (int q = 0; q < DIN / 4; q++) {                                      \
                fma2(a0,  (XB)[2 * q],     wpA[2 * q]);                              \
                fma2(a1r, (XB)[2 * q + 1], wpA[2 * q + 1]);                          \
                fma2(bb0, (XB)[2 * q],     wpB[2 * q]);                              \
                fma2(bb1, (XB)[2 * q + 1], wpB[2 * q + 1]);                          \
            }                                                                        \
            const float driveA = sum2(a0, a1r);                                      \
            const float driveB = sum2(bb0, bb1);                                     \
            m1A = fmaf(m1A, a1, driveA);                                             \
            const float s1A = (m1A > 0.5f) ? 1.0f : 0.0f;                            \
            m1A = fmaf(s1A, -0.5f, m1A);                                             \
            m1B = fmaf(m1B, a1, driveB);                                             \
            const float s1B = (m1B > 0.5f) ? 1.0f : 0.0f;                            \
            m1B = fmaf(s1B, -0.5f, m1B);                                             \
            *pS = make_float2(s1A, s1B);  pS += DH / 2;                              \
            *pM = make_float2(m1A, m1B);  pM += DH / 2;                              \
            float px = s1A * w20A; px = fmaf(s1B, w20B, px);                         \
            float py = s1A * w21A; py = fmaf(s1B, w21B, py);                         \
            *pP = make_float2(px, py);                                               \
            pP += PADR;                                                              \
        } while (0)

        for (int ch = 0; ch < NCHUNK; ch++) {
            const int buf = ch & 1;
            const int u   = ch >> 1;

            asm volatile("cp.async.wait_group 0;");            // x[ch] landed
            asm volatile("bar.sync 5, 128;" ::: "memory");     // + sub1(ch-1) STS done
            if (tid == 0) {
                asm volatile("fence.proxy.async.shared::cta;" ::: "memory");
                if (ch > 0) {
                    const int pc = ch - 1;
                    bulk_store(s1p + ((size_t)pc * CHUNK + HALF) * DH,
                               smem_base + OFF_S1T + TILE_B, TILE_B);
                    bulk_store(m1p + ((size_t)pc * CHUNK + HALF) * DH,
                               smem_base + OFF_M1T + TILE_B, TILE_B);
                    asm volatile("cp.async.bulk.commit_group;");
                }
                asm volatile("cp.async.bulk.wait_group 1;");   // sub0(ch-1) drained
            }
            asm volatile("bar.sync 5, 128;" ::: "memory");     // sub0 writable; x usable

            if (ch + 1 < NCHUNK) {
                const float* g = xrow + (size_t)(ch + 1) * CHUNK * DIN + tid * 8;
                const unsigned s = xs_sa + ((ch + 1) & 1) * XS_BYTES + tid * 32;
                cp16(s, g);
                cp16(s + 16, g + 4);
            }
            asm volatile("cp.async.commit_group;");

            if (ch >= 2)
                mbar_wait(buf ? mbE1 : mbE0, (unsigned)((u & 1) ^ 1));

            const unsigned xbase = xs_sa + buf * XS_BYTES;
            float2* pS = (float2*)(smem_raw + OFF_S1T) + tid;
            float2* pM = (float2*)(smem_raw + OFF_M1T) + tid;
            float2* pP = part + (size_t)buf * PART_F2 + tid;

            if (lact) {
                // ---- half 0: steps 0..15 -> sub-tile 0 ----
                unsigned long long x0[16], x1[16];
                ld16v(x0, xbase);
                for (int tt = 0; tt < HALF; tt += 2) {
                    ld16v(x1, xbase + (tt + 1) * (DIN * 4));
                    STEP_BODY(x0);
                    if (tt + 2 < HALF) ld16v(x0, xbase + (tt + 2) * (DIN * 4));
                    STEP_BODY(x1);
                }
            }
            asm volatile("bar.sync 5, 128;" ::: "memory");     // sub0 STS done
            if (tid == 0) {
                asm volatile("fence.proxy.async.shared::cta;" ::: "memory");
                bulk_store(s1p + (size_t)ch * CHUNK * DH, smem_base + OFF_S1T, TILE_B);
                bulk_store(m1p + (size_t)ch * CHUNK * DH, smem_base + OFF_M1T, TILE_B);
                asm volatile("cp.async.bulk.commit_group;");
                asm volatile("cp.async.bulk.wait_group 1;");   // sub1(ch-1) drained
            }
            asm volatile("bar.sync 5, 128;" ::: "memory");     // sub1 writable

            if (lact) {
                // ---- half 1: steps 16..31 -> sub-tile 1 ----
                pS = (float2*)(smem_raw + OFF_S1T + TILE_B) + tid;
                pM = (float2*)(smem_raw + OFF_M1T + TILE_B) + tid;
                unsigned long long x0[16], x1[16];
                ld16v(x0, xbase + HALF * (DIN * 4));
                for (int tt = HALF; tt < CHUNK; tt += 2) {
                    ld16v(x1, xbase + (tt + 1) * (DIN * 4));
                    STEP_BODY(x0);
                    if (tt + 2 < CHUNK) ld16v(x0, xbase + (tt + 2) * (DIN * 4));
                    STEP_BODY(x1);
                }
            }
            __syncwarp();
            if ((tid & 31) == 0)
                mbar_arrive(buf ? mbF1 : mbF0);   // partials[buf] full
        }
        #undef STEP_BODY

        // flush last chunk's sub-tile 1
        asm volatile("bar.sync 5, 128;" ::: "memory");
        if (tid == 0) {
            asm volatile("fence.proxy.async.shared::cta;" ::: "memory");
            const int pc = NCHUNK - 1;
            bulk_store(s1p + ((size_t)pc * CHUNK + HALF) * DH,
                       smem_base + OFF_S1T + TILE_B, TILE_B);
            bulk_store(m1p + ((size_t)pc * CHUNK + HALF) * DH,
                       smem_base + OFF_M1T + TILE_B, TILE_B);
            asm volatile("cp.async.bulk.commit_group;");
            asm volatile("cp.async.bulk.wait_group 0;");
        }
    } else {
        // ================= CONSUMER (layer 2) =================
        const int lane = tid - NPROD;             // lane = timestep within chunk
        const float b2x = b2[0], b2y = b2[1];
        float m2x = 0.f, m2y = 0.f, os0 = 0.f, os1 = 0.f;
        float f0 = 0.f, f1 = 0.f;                 // m2s[t=0] per channel

        for (int ch = 0; ch < NCHUNK; ch++) {
            const int buf = ch & 1;
            const int u   = ch >> 1;
            mbar_wait(buf ? mbF1 : mbF0, (unsigned)(u & 1));

            const float2* pf = part + (size_t)buf * PART_F2 + lane * PADR;
            float ax0 = 0.f, ay0 = 0.f, ax1 = 0.f, ay1 = 0.f;
            #pragma unroll 4
            for (int j = 0; j < NACT; j += 2) {
                float2 v0 = pf[j], v1 = pf[j + 1];
                ax0 += v0.x; ay0 += v0.y;
                ax1 += v1.x; ay1 += v1.y;
            }
            const float sx = ax0 + ax1;
            const float sy = ay0 + ay1;

            __syncwarp();
            if (lane == 0)
                mbar_arrive(buf ? mbE1 : mbE0);   // partials[buf] free

            float rA[CHUNK], rB[CHUNK];
            #pragma unroll
            for (int t2 = 0; t2 < CHUNK; t2++) {
                rA[t2] = __shfl_sync(0xffffffffu, sx, t2) + b2x;
                rB[t2] = __shfl_sync(0xffffffffu, sy, t2) + b2y;
            }

            float capS0 = 0.f, capS1 = 0.f, capM0 = 0.f, capM1 = 0.f;
            #pragma unroll
            for (int t2 = 0; t2 < CHUNK; t2++) {
                m2x = fmaf(m2x, a2, rA[t2]);
                const float sA = (m2x > 1.0f) ? 1.0f : 0.0f;
                m2x -= sA;
                m2y = fmaf(m2y, a2, rB[t2]);
                const float sB = (m2y > 1.0f) ? 1.0f : 0.0f;
                m2y -= sB;
                os0 += m2x; os1 += m2y;
                if (lane == t2) { capS0 = sA; capS1 = sB; capM0 = m2x; capM1 = m2y; }
            }
            const int gt = ch * CHUNK + lane;
            __stcs((float2*)(s2p + (size_t)gt * DOUT), make_float2(capS0, capS1));
            __stcs((float2*)(m2p + (size_t)gt * DOUT), make_float2(capM0, capM1));

            if (ch == 0) {
                f0 = __shfl_sync(0xffffffffu, capM0, 0);
                f1 = __shfl_sync(0xffffffffu, capM1, 0);
            }
        }
        if (lane == 0) {
            out_o[b * DOUT + 0] = (os0 - f0) * (1.0f / (float)T_);
            out_o[b * DOUT + 1] = (os1 - f1) * (1.0f / (float)T_);
        }
    }
}

extern "C" void kernel_launch(void* const* d_in, const int* in_sizes, int n_in,
                              void* d_out, int out_size) {
    const float* x  = (const float*)d_in[0];
    const float* W1 = (const float*)d_in[1];
    const float* b1 = (const float*)d_in[2];
    const float* W2 = (const float*)d_in[3];
    const float* b2 = (const float*)d_in[4];

    const float a1 = (float)exp((double)(-1.0f / 10.0f));
    const float a2 = (float)exp((double)(-1.0f / 20.0f));

    cudaFuncSetAttribute(snn_kernel,
                         cudaFuncAttributeMaxDynamicSharedMemorySize, SMEM_TOTAL);
    snn_kernel<<<B_, NTHR, SMEM_TOTAL>>>(x, W1, b1, W2, b2, (float*)d_out, a1, a2);
}